// round 2
// baseline (speedup 1.0000x reference)
#include <cuda_runtime.h>
#include <cstdint>

// NetNew_17162689315115 — R2: 2 rows/thread, packed f32x2 FMA (FFMA2),
// weights pre-duplicated (w,w) in shared so one LDS.128 feeds 2 FFMA2.

typedef unsigned long long u64;

struct NetParams {
    const float* W[9];   // W1..W8, Wf
    const float* x;
    float*       out;
    int          B;
};

template <int L> struct LayerCfg {
    static constexpr int DIN  = 8 + 9 * L;
    static constexpr int DPAD = (DIN + 3) & ~3;
    static constexpr int BASE = 72 - 9 * L;     // start of current h in buffer
};

template <int L> struct WOff;
template <> struct WOff<0> { static constexpr int V = 0; };
template <int L> struct WOff {
    static constexpr int V = WOff<L - 1>::V + 13 * LayerCfg<L - 1>::DPAD;
};
static constexpr int WF_OFF   = WOff<7>::V + 13 * LayerCfg<7>::DPAD; // 4264 pairs
static constexpr int SM_PAIRS = WF_OFF + 80;                         // 4344 pairs = 34752 B

// ---- packed f32x2 primitives (sm_100+/sm_103a) ----
__device__ __forceinline__ u64 fma2(u64 a, u64 b, u64 c) {
    u64 d;
    asm("fma.rn.f32x2 %0, %1, %2, %3;" : "=l"(d) : "l"(a), "l"(b), "l"(c));
    return d;
}
__device__ __forceinline__ u64 add2(u64 a, u64 b) {
    u64 d;
    asm("add.rn.f32x2 %0, %1, %2;" : "=l"(d) : "l"(a), "l"(b));
    return d;
}
__device__ __forceinline__ u64 sub2(u64 a, u64 b) {
    u64 d;
    asm("sub.rn.f32x2 %0, %1, %2;" : "=l"(d) : "l"(a), "l"(b));
    return d;
}
__device__ __forceinline__ u64 mul2(u64 a, u64 b) {
    u64 d;
    asm("mul.rn.f32x2 %0, %1, %2;" : "=l"(d) : "l"(a), "l"(b));
    return d;
}
__device__ __forceinline__ u64 pack2(float lo, float hi) {
    u64 v;
    asm("mov.b64 %0, {%1, %2};" : "=l"(v) : "f"(lo), "f"(hi));
    return v;
}
__device__ __forceinline__ void unpack2(u64 v, float& lo, float& hi) {
    asm("mov.b64 {%0, %1}, %2;" : "=f"(lo), "=f"(hi) : "l"(v));
}

__device__ __forceinline__ float clip_mag(float v, float mx) {
    // matches jnp.where(|v| >= mx, v * |mx/v|, v) incl. inf -> NaN edge case
    if (fabsf(v) >= mx) v = v * fabsf(mx / v);
    return v;
}

template <int L>
__device__ __forceinline__ void do_layer(u64* __restrict__ h,
                                         const u64* __restrict__ smw) {
    constexpr int DP   = LayerCfg<L>::DPAD;
    constexpr int BASE = LayerCfg<L>::BASE;
    const u64* wl = smw + WOff<L>::V;

    u64 z[13];
#pragma unroll
    for (int j = 0; j < 13; ++j) {
        u64 acc = 0ull;  // (0.0f, 0.0f)
#pragma unroll
        for (int k = 0; k < DP; k += 2) {
            ulonglong2 w = *reinterpret_cast<const ulonglong2*>(wl + j * DP + k);
            acc = fma2(w.x, h[BASE + k + 0], acc);
            acc = fma2(w.y, h[BASE + k + 1], acc);
        }
        z[j] = acc;
    }

    u64* o = h + (BASE - 9);
    // '+'
    o[0] = add2(z[0], z[1]);
    // '-'
    o[1] = sub2(z[2], z[3]);
    // '*' clip at 99999999
    {
        u64 m = mul2(z[4], z[5]);
        float a, b; unpack2(m, a, b);
        o[2] = pack2(clip_mag(a, 99999999.0f), clip_mag(b, 99999999.0f));
    }
    // '/' denom fix at exactly 0, clip at 9999
    {
        float a0, a1, b0, b1;
        unpack2(z[6], a0, a1);
        unpack2(z[7], b0, b1);
        float d0 = (b0 == 0.0f) ? (b0 + 0.0001f) : b0;
        float d1 = (b1 == 0.0f) ? (b1 + 0.0001f) : b1;
        o[3] = pack2(clip_mag(a0 / d0, 9999.0f), clip_mag(a1 / d1, 9999.0f));
    }
    // sin / cos
    {
        float a, b; unpack2(z[8], a, b);
        o[4] = pack2(sinf(a), sinf(b));
    }
    {
        float a, b; unpack2(z[9], a, b);
        o[5] = pack2(cosf(a), cosf(b));
    }
    // exp with upper clamp at 17
    {
        float a, b; unpack2(z[10], a, b);
        if (a >= 17.0f) a = a * (17.0f / a);
        if (b >= 17.0f) b = b * (17.0f / b);
        o[6] = pack2(expf(a), expf(b));
    }
    // log(|a|)
    {
        float a, b; unpack2(z[11], a, b);
        o[7] = pack2(logf(fabsf(a)), logf(fabsf(b)));
    }
    // square, clip at 99999999
    {
        u64 m = mul2(z[12], z[12]);
        float a, b; unpack2(m, a, b);
        o[8] = pack2(clip_mag(a, 99999999.0f), clip_mag(b, 99999999.0f));
    }
}

__global__ __launch_bounds__(256)
void netnew_kernel2(NetParams p) {
    __shared__ __align__(16) u64 smw[SM_PAIRS];

    // ---- stage duplicated weights (w,w) into shared, rows padded/zero ----
#define STAGE_LAYER(L)                                                        \
    {                                                                         \
        constexpr int D  = LayerCfg<L>::DIN;                                  \
        constexpr int DP = LayerCfg<L>::DPAD;                                 \
        const float* g = p.W[L];                                              \
        for (int i = threadIdx.x; i < 13 * DP; i += blockDim.x) {             \
            int r = i / DP, c = i - r * DP;                                   \
            float v = (c < D) ? g[r * D + c] : 0.0f;                          \
            smw[WOff<L>::V + i] = pack2(v, v);                                \
        }                                                                     \
    }
    STAGE_LAYER(0) STAGE_LAYER(1) STAGE_LAYER(2) STAGE_LAYER(3)
    STAGE_LAYER(4) STAGE_LAYER(5) STAGE_LAYER(6) STAGE_LAYER(7)
#undef STAGE_LAYER
    for (int i = threadIdx.x; i < 80; i += blockDim.x) {
        float v = p.W[8][i];
        smw[WF_OFF + i] = pack2(v, v);
    }
    __syncthreads();

    const int t  = blockIdx.x * blockDim.x + threadIdx.x;
    const int r0 = 2 * t;
    if (r0 >= p.B) return;

    // h[i] = (row r0 feature i, row r0+1 feature i), packed.
    // Layout: [outs8, outs7, ..., outs1, x]; x at [72..79]; pads [80..83]=0.
    u64 h[84];
    {
        const float4* xr = reinterpret_cast<const float4*>(p.x + (size_t)r0 * 8);
        float4 a0 = xr[0], a1 = xr[1];   // row r0
        float4 b0 = xr[2], b1 = xr[3];   // row r0+1
        h[72] = pack2(a0.x, b0.x); h[73] = pack2(a0.y, b0.y);
        h[74] = pack2(a0.z, b0.z); h[75] = pack2(a0.w, b0.w);
        h[76] = pack2(a1.x, b1.x); h[77] = pack2(a1.y, b1.y);
        h[78] = pack2(a1.z, b1.z); h[79] = pack2(a1.w, b1.w);
        h[80] = 0ull; h[81] = 0ull; h[82] = 0ull; h[83] = 0ull;
    }

    do_layer<0>(h, smw);
    do_layer<1>(h, smw);
    do_layer<2>(h, smw);
    do_layer<3>(h, smw);
    do_layer<4>(h, smw);
    do_layer<5>(h, smw);
    do_layer<6>(h, smw);
    do_layer<7>(h, smw);

    // final: out = dot(Wf, h[0..79]) for both rows at once
    u64 acc = 0ull;
#pragma unroll
    for (int k = 0; k < 80; k += 2) {
        ulonglong2 w = *reinterpret_cast<const ulonglong2*>(smw + WF_OFF + k);
        acc = fma2(w.x, h[k + 0], acc);
        acc = fma2(w.y, h[k + 1], acc);
    }
    float va, vb; unpack2(acc, va, vb);
    p.out[r0]     = va;
    p.out[r0 + 1] = vb;
}

extern "C" void kernel_launch(void* const* d_in, const int* in_sizes, int n_in,
                              void* d_out, int out_size) {
    NetParams p;
    p.x = (const float*)d_in[0];
    for (int i = 0; i < 9; ++i) p.W[i] = (const float*)d_in[1 + i];
    p.out = (float*)d_out;
    p.B   = in_sizes[0] / 8;

    const int threads = 256;
    const int pairs   = p.B / 2;
    const int blocks  = (pairs + threads - 1) / threads;
    netnew_kernel2<<<blocks, threads>>>(p);
}

// round 4
// speedup vs baseline: 1.2328x; 1.2328x over previous
#include <cuda_runtime.h>

// NetNew_17162689315115 — R4: k-outer / j-inner GEMV with 13 register
// accumulators; h streamed from per-thread local memory (read 1x per layer);
// weights transposed in shared (wT[k][j], row stride 16 floats).
// Per-z accumulation order identical to R1 (sequential k) -> same numerics.

struct NetParams {
    const float* W[9];   // W1..W8, Wf
    const float* x;
    float*       out;
    int          B;
};

// Per-layer dims: DIN[L] = 8 + 9L. Transposed block: 16*DIN floats.
template <int L> struct LC { static constexpr int DIN = 8 + 9 * L; };
template <int L> struct WOff;
template <> struct WOff<0> { static constexpr int V = 0; };
template <int L> struct WOff {
    static constexpr int V = WOff<L - 1>::V + 16 * LC<L - 1>::DIN;
};
static constexpr int WF_OFF    = WOff<7>::V + 16 * LC<7>::DIN;  // 5056
static constexpr int SM_FLOATS = WF_OFF + 80;                   // 5136 (~20.5KB)

__device__ __forceinline__ float clip_mag(float v, float mx) {
    // matches jnp.where(|v| >= mx, v * |mx/v|, v) incl. inf -> NaN edge case
    if (fabsf(v) >= mx) v = v * fabsf(mx / v);
    return v;
}

__global__ __launch_bounds__(256, 4)
void netnew_kernel4(NetParams p) {
    __shared__ __align__(16) float smw[SM_FLOATS];

    // ---- stage transposed weights: smw[OFF_L + 16k + j] = W_L[j*DIN + k] ----
#define STAGE_LAYER(L)                                                        \
    {                                                                         \
        constexpr int D = LC<L>::DIN;                                         \
        const float* g = p.W[L];                                              \
        for (int i = threadIdx.x; i < 16 * D; i += blockDim.x) {              \
            int k = i >> 4, j = i & 15;                                       \
            smw[WOff<L>::V + i] = (j < 13) ? g[j * D + k] : 0.0f;             \
        }                                                                     \
    }
    STAGE_LAYER(0) STAGE_LAYER(1) STAGE_LAYER(2) STAGE_LAYER(3)
    STAGE_LAYER(4) STAGE_LAYER(5) STAGE_LAYER(6) STAGE_LAYER(7)
#undef STAGE_LAYER
    for (int i = threadIdx.x; i < 80; i += blockDim.x)
        smw[WF_OFF + i] = p.W[8][i];
    __syncthreads();

    const int row = blockIdx.x * blockDim.x + threadIdx.x;
    if (row >= p.B) return;

    // h in per-thread local memory (dynamic indexing forces local).
    // Layout: [outs8 | outs7 | ... | outs1 | x]; x at [72..79].
    float hl[80];
    {
        const float4* xr = reinterpret_cast<const float4*>(p.x + (size_t)row * 8);
        float4 a = xr[0], b = xr[1];
        hl[72] = a.x; hl[73] = a.y; hl[74] = a.z; hl[75] = a.w;
        hl[76] = b.x; hl[77] = b.y; hl[78] = b.z; hl[79] = b.w;
    }

    int BASE = 72;      // first input feature of current layer
    int DIN  = 8;
    int woff = 0;

#pragma unroll 1
    for (int Lyr = 0; Lyr < 8; ++Lyr) {
        const float* wL = smw + woff;

        float z0 = 0.f, z1 = 0.f, z2 = 0.f, z3 = 0.f, z4 = 0.f, z5 = 0.f,
              z6 = 0.f, z7 = 0.f, z8 = 0.f, z9 = 0.f, z10 = 0.f, z11 = 0.f,
              z12 = 0.f;

#pragma unroll 1
        for (int k = 0; k < DIN; ++k) {
            float hk = hl[BASE + k];
            const float4 wa = *reinterpret_cast<const float4*>(wL + 16 * k);
            const float4 wb = *reinterpret_cast<const float4*>(wL + 16 * k + 4);
            const float4 wc = *reinterpret_cast<const float4*>(wL + 16 * k + 8);
            const float  wd = wL[16 * k + 12];
            z0  = fmaf(wa.x, hk, z0);
            z1  = fmaf(wa.y, hk, z1);
            z2  = fmaf(wa.z, hk, z2);
            z3  = fmaf(wa.w, hk, z3);
            z4  = fmaf(wb.x, hk, z4);
            z5  = fmaf(wb.y, hk, z5);
            z6  = fmaf(wb.z, hk, z6);
            z7  = fmaf(wb.w, hk, z7);
            z8  = fmaf(wc.x, hk, z8);
            z9  = fmaf(wc.y, hk, z9);
            z10 = fmaf(wc.z, hk, z10);
            z11 = fmaf(wc.w, hk, z11);
            z12 = fmaf(wd,   hk, z12);
        }

        // ---- elementwise ops (identical scalar code/order to R1) ----
        const int ob = BASE - 9;
        hl[ob + 0] = z0 + z1;
        hl[ob + 1] = z2 - z3;
        hl[ob + 2] = clip_mag(z4 * z5, 99999999.0f);
        {
            float den = (z7 == 0.0f) ? (z7 + 0.0001f) : z7;
            hl[ob + 3] = clip_mag(z6 / den, 9999.0f);
        }
        hl[ob + 4] = sinf(z8);
        hl[ob + 5] = cosf(z9);
        {
            float a = z10;
            if (a >= 17.0f) a = a * (17.0f / a);
            hl[ob + 6] = expf(a);
        }
        hl[ob + 7] = logf(fabsf(z11));
        hl[ob + 8] = clip_mag(z12 * z12, 99999999.0f);

        woff += 16 * DIN;
        BASE -= 9;
        DIN  += 9;
    }

    // ---- final: out = dot(Wf, h[0..79]), sequential k ----
    float acc = 0.0f;
#pragma unroll 1
    for (int k = 0; k < 80; ++k)
        acc = fmaf(smw[WF_OFF + k], hl[k], acc);
    p.out[row] = acc;
}

extern "C" void kernel_launch(void* const* d_in, const int* in_sizes, int n_in,
                              void* d_out, int out_size) {
    NetParams p;
    p.x = (const float*)d_in[0];
    for (int i = 0; i < 9; ++i) p.W[i] = (const float*)d_in[1 + i];
    p.out = (float*)d_out;
    p.B   = in_sizes[0] / 8;

    const int threads = 256;
    const int blocks  = (p.B + threads - 1) / threads;
    netnew_kernel4<<<blocks, threads>>>(p);
}

// round 5
// speedup vs baseline: 1.2879x; 1.0447x over previous
#include <cuda_runtime.h>

// NetNew_17162689315115 — R5 hybrid: fully-unrolled layers, h[80] register-
// resident (compile-time indices), k-outer/j-inner GEMV with 13 independent
// accumulator chains, transposed weights in shared (row stride 16 floats).
// Per-z accumulation order = sequential ascending k (identical to R1 numerics).

struct NetParams {
    const float* W[9];   // W1..W8, Wf
    const float* x;
    float*       out;
    int          B;
};

template <int L> struct LC {
    static constexpr int DIN  = 8 + 9 * L;
    static constexpr int BASE = 72 - 9 * L;   // first input feature index
};
template <int L> struct WOff;
template <> struct WOff<0> { static constexpr int V = 0; };
template <int L> struct WOff {
    static constexpr int V = WOff<L - 1>::V + 16 * LC<L - 1>::DIN;
};
static constexpr int WF_OFF    = WOff<7>::V + 16 * LC<7>::DIN;  // 5056
static constexpr int SM_FLOATS = WF_OFF + 80;                   // 5136 (~20.5KB)

__device__ __forceinline__ float clip_mag(float v, float mx) {
    // matches jnp.where(|v| >= mx, v * |mx/v|, v) incl. inf -> NaN edge case
    if (fabsf(v) >= mx) v = v * fabsf(mx / v);
    return v;
}

template <int L>
__device__ __forceinline__ void do_layer(float* __restrict__ h,
                                         const float* __restrict__ smw) {
    constexpr int DIN  = LC<L>::DIN;
    constexpr int BASE = LC<L>::BASE;
    const float* wl = smw + WOff<L>::V;

    float z[13];
#pragma unroll
    for (int j = 0; j < 13; ++j) z[j] = 0.0f;

#pragma unroll
    for (int k = 0; k < DIN; ++k) {
        const float hk = h[BASE + k];
        const float4 wa = *reinterpret_cast<const float4*>(wl + 16 * k);
        const float4 wb = *reinterpret_cast<const float4*>(wl + 16 * k + 4);
        const float4 wc = *reinterpret_cast<const float4*>(wl + 16 * k + 8);
        const float  wd = wl[16 * k + 12];
        z[0]  = fmaf(wa.x, hk, z[0]);
        z[1]  = fmaf(wa.y, hk, z[1]);
        z[2]  = fmaf(wa.z, hk, z[2]);
        z[3]  = fmaf(wa.w, hk, z[3]);
        z[4]  = fmaf(wb.x, hk, z[4]);
        z[5]  = fmaf(wb.y, hk, z[5]);
        z[6]  = fmaf(wb.z, hk, z[6]);
        z[7]  = fmaf(wb.w, hk, z[7]);
        z[8]  = fmaf(wc.x, hk, z[8]);
        z[9]  = fmaf(wc.y, hk, z[9]);
        z[10] = fmaf(wc.z, hk, z[10]);
        z[11] = fmaf(wc.w, hk, z[11]);
        z[12] = fmaf(wd,   hk, z[12]);
    }

    float* o = h + (BASE - 9);
    o[0] = z[0] + z[1];
    o[1] = z[2] - z[3];
    o[2] = clip_mag(z[4] * z[5], 99999999.0f);
    {
        float b   = z[7];
        float den = (b == 0.0f) ? (b + 0.0001f) : b;
        o[3] = clip_mag(z[6] / den, 9999.0f);
    }
    o[4] = sinf(z[8]);
    o[5] = cosf(z[9]);
    {
        float a = z[10];
        if (a >= 17.0f) a = a * (17.0f / a);
        o[6] = expf(a);
    }
    o[7] = logf(fabsf(z[11]));
    o[8] = clip_mag(z[12] * z[12], 99999999.0f);
}

__global__ __launch_bounds__(256, 2)
void netnew_kernel5(NetParams p) {
    __shared__ __align__(16) float smw[SM_FLOATS];

    // ---- stage transposed weights: smw[OFF_L + 16k + j] = W_L[j*DIN + k] ----
#define STAGE_LAYER(L)                                                        \
    {                                                                         \
        constexpr int D = LC<L>::DIN;                                         \
        const float* g = p.W[L];                                              \
        for (int i = threadIdx.x; i < 16 * D; i += blockDim.x) {              \
            int k = i >> 4, j = i & 15;                                       \
            smw[WOff<L>::V + i] = (j < 13) ? g[j * D + k] : 0.0f;             \
        }                                                                     \
    }
    STAGE_LAYER(0) STAGE_LAYER(1) STAGE_LAYER(2) STAGE_LAYER(3)
    STAGE_LAYER(4) STAGE_LAYER(5) STAGE_LAYER(6) STAGE_LAYER(7)
#undef STAGE_LAYER
    for (int i = threadIdx.x; i < 80; i += blockDim.x)
        smw[WF_OFF + i] = p.W[8][i];
    __syncthreads();

    const int row = blockIdx.x * blockDim.x + threadIdx.x;
    if (row >= p.B) return;

    // h register-resident: [outs8 | outs7 | ... | outs1 | x]; x at [72..79].
    float h[80];
    {
        const float4* xr = reinterpret_cast<const float4*>(p.x + (size_t)row * 8);
        float4 a = xr[0], b = xr[1];
        h[72] = a.x; h[73] = a.y; h[74] = a.z; h[75] = a.w;
        h[76] = b.x; h[77] = b.y; h[78] = b.z; h[79] = b.w;
    }

    do_layer<0>(h, smw);
    do_layer<1>(h, smw);
    do_layer<2>(h, smw);
    do_layer<3>(h, smw);
    do_layer<4>(h, smw);
    do_layer<5>(h, smw);
    do_layer<6>(h, smw);
    do_layer<7>(h, smw);

    // ---- final: out = dot(Wf, h[0..79]), sequential ascending k ----
    float acc = 0.0f;
#pragma unroll
    for (int k = 0; k < 80; k += 4) {
        float4 w = *reinterpret_cast<const float4*>(smw + WF_OFF + k);
        acc = fmaf(w.x, h[k + 0], acc);
        acc = fmaf(w.y, h[k + 1], acc);
        acc = fmaf(w.z, h[k + 2], acc);
        acc = fmaf(w.w, h[k + 3], acc);
    }
    p.out[row] = acc;
}

extern "C" void kernel_launch(void* const* d_in, const int* in_sizes, int n_in,
                              void* d_out, int out_size) {
    NetParams p;
    p.x = (const float*)d_in[0];
    for (int i = 0; i < 9; ++i) p.W[i] = (const float*)d_in[1 + i];
    p.out = (float*)d_out;
    p.B   = in_sizes[0] / 8;

    const int threads = 256;
    const int blocks  = (p.B + threads - 1) / threads;
    netnew_kernel5<<<blocks, threads>>>(p);
}

// round 6
// speedup vs baseline: 1.5472x; 1.2013x over previous
#include <cuda_runtime.h>

// NetNew_17162689315115 — R6: weights in __constant__ (LDC.128, immediate
// offsets, separate constant port) instead of shared (LDS via contended L1).
// j-outer GEMV, h[84] register-resident, fully unrolled, numerics == R1.

struct NetParams {
    const float* x;
    float*       out;
    int          B;
};
struct PrepParams {
    const float* W[9];   // W1..W8, Wf
};

template <int L> struct LC {
    static constexpr int DIN  = 8 + 9 * L;
    static constexpr int DPAD = (DIN + 3) & ~3;
    static constexpr int BASE = 72 - 9 * L;   // first input feature index
};
template <int L> struct WOff;
template <> struct WOff<0> { static constexpr int V = 0; };
template <int L> struct WOff {
    static constexpr int V = WOff<L - 1>::V + 13 * LC<L - 1>::DPAD;
};
static constexpr int WF_OFF   = WOff<7>::V + 13 * LC<7>::DPAD;  // 4264
static constexpr int CW_TOTAL = WF_OFF + 80;                    // 4344 floats

__constant__ __align__(16) float cw[CW_TOTAL];
__device__   __align__(16) float g_wpad[CW_TOTAL];

__device__ __forceinline__ float clip_mag(float v, float mx) {
    // matches jnp.where(|v| >= mx, v * |mx/v|, v) incl. inf -> NaN edge case
    if (fabsf(v) >= mx) v = v * fabsf(mx / v);
    return v;
}

// ---- prep: pad each W row to DPAD (zero fill), append Wf ----
__global__ void netnew_prep(PrepParams pp) {
#define STAGE_LAYER(L)                                                        \
    {                                                                         \
        constexpr int D  = LC<L>::DIN;                                        \
        constexpr int DP = LC<L>::DPAD;                                       \
        const float* g = pp.W[L];                                             \
        for (int i = threadIdx.x; i < 13 * DP; i += blockDim.x) {             \
            int r = i / DP, c = i - r * DP;                                   \
            g_wpad[WOff<L>::V + i] = (c < D) ? g[r * D + c] : 0.0f;           \
        }                                                                     \
    }
    STAGE_LAYER(0) STAGE_LAYER(1) STAGE_LAYER(2) STAGE_LAYER(3)
    STAGE_LAYER(4) STAGE_LAYER(5) STAGE_LAYER(6) STAGE_LAYER(7)
#undef STAGE_LAYER
    for (int i = threadIdx.x; i < 80; i += blockDim.x)
        g_wpad[WF_OFF + i] = pp.W[8][i];
}

template <int L>
__device__ __forceinline__ void do_layer(float* __restrict__ h) {
    constexpr int DP   = LC<L>::DPAD;
    constexpr int BASE = LC<L>::BASE;

    float z[13];
#pragma unroll
    for (int j = 0; j < 13; ++j) {
        float acc = 0.0f;
#pragma unroll
        for (int k = 0; k < DP; k += 4) {
            const float4 w =
                *reinterpret_cast<const float4*>(cw + WOff<L>::V + j * DP + k);
            acc = fmaf(w.x, h[BASE + k + 0], acc);
            acc = fmaf(w.y, h[BASE + k + 1], acc);
            acc = fmaf(w.z, h[BASE + k + 2], acc);
            acc = fmaf(w.w, h[BASE + k + 3], acc);
        }
        z[j] = acc;
    }

    float* o = h + (BASE - 9);
    o[0] = z[0] + z[1];
    o[1] = z[2] - z[3];
    o[2] = clip_mag(z[4] * z[5], 99999999.0f);
    {
        float b   = z[7];
        float den = (b == 0.0f) ? (b + 0.0001f) : b;
        o[3] = clip_mag(z[6] / den, 9999.0f);
    }
    o[4] = sinf(z[8]);
    o[5] = cosf(z[9]);
    {
        float a = z[10];
        if (a >= 17.0f) a = a * (17.0f / a);
        o[6] = expf(a);
    }
    o[7] = logf(fabsf(z[11]));
    o[8] = clip_mag(z[12] * z[12], 99999999.0f);
}

__global__ __launch_bounds__(256, 2)
void netnew_kernel6(NetParams p) {
    const int row = blockIdx.x * blockDim.x + threadIdx.x;
    if (row >= p.B) return;

    // h layout: [outs8 | outs7 | ... | outs1 | x]; x at [72..79];
    // [80..83] zero pads read by padded (zero) weight lanes.
    float h[84];
    {
        const float4* xr = reinterpret_cast<const float4*>(p.x + (size_t)row * 8);
        float4 a = xr[0], b = xr[1];
        h[72] = a.x; h[73] = a.y; h[74] = a.z; h[75] = a.w;
        h[76] = b.x; h[77] = b.y; h[78] = b.z; h[79] = b.w;
        h[80] = 0.0f; h[81] = 0.0f; h[82] = 0.0f; h[83] = 0.0f;
    }

    do_layer<0>(h);
    do_layer<1>(h);
    do_layer<2>(h);
    do_layer<3>(h);
    do_layer<4>(h);
    do_layer<5>(h);
    do_layer<6>(h);
    do_layer<7>(h);

    // final: out = dot(Wf, h[0..79]), sequential ascending k
    float acc = 0.0f;
#pragma unroll
    for (int k = 0; k < 80; k += 4) {
        const float4 w = *reinterpret_cast<const float4*>(cw + WF_OFF + k);
        acc = fmaf(w.x, h[k + 0], acc);
        acc = fmaf(w.y, h[k + 1], acc);
        acc = fmaf(w.z, h[k + 2], acc);
        acc = fmaf(w.w, h[k + 3], acc);
    }
    p.out[row] = acc;
}

extern "C" void kernel_launch(void* const* d_in, const int* in_sizes, int n_in,
                              void* d_out, int out_size) {
    PrepParams pp;
    for (int i = 0; i < 9; ++i) pp.W[i] = (const float*)d_in[1 + i];

    NetParams p;
    p.x   = (const float*)d_in[0];
    p.out = (float*)d_out;
    p.B   = in_sizes[0] / 8;

    // 1) pad/stage weights into device scratch
    netnew_prep<<<1, 256>>>(pp);

    // 2) copy scratch -> constant bank (device-to-device, graph-capturable)
    void* src = nullptr;
    cudaGetSymbolAddress(&src, g_wpad);
    cudaMemcpyToSymbolAsync(cw, src, CW_TOTAL * sizeof(float), 0,
                            cudaMemcpyDeviceToDevice, 0);

    // 3) main kernel
    const int threads = 256;
    const int blocks  = (p.B + threads - 1) / threads;
    netnew_kernel6<<<blocks, threads>>>(p);
}

// round 7
// speedup vs baseline: 1.5996x; 1.0339x over previous
#include <cuda_runtime.h>

// NetNew_17162689315115 — R7: R6 (weights in __constant__, LDC.128) +
// occupancy fix: 96-thread blocks, launch_bounds(96,7) -> 21 warps/SM
// (reg-file limit), and exact-DIN tails (no padded FMAs, no pad registers).

struct NetParams {
    const float* x;
    float*       out;
    int          B;
};
struct PrepParams {
    const float* W[9];   // W1..W8, Wf
};

template <int L> struct LC {
    static constexpr int DIN  = 8 + 9 * L;
    static constexpr int BASE = 72 - 9 * L;   // first input feature index
};
template <int L> struct WOff;
template <> struct WOff<0> { static constexpr int V = 0; };
template <int L> struct WOff {
    static constexpr int V = WOff<L - 1>::V + 13 * LC<L - 1>::DIN;
};
static constexpr int WF_OFF   = WOff<7>::V + 13 * LC<7>::DIN;  // 13*316
static constexpr int CW_TOTAL = WF_OFF + 80;

__constant__ __align__(16) float cw[CW_TOTAL];
__device__   __align__(16) float g_wpad[CW_TOTAL];

__device__ __forceinline__ float clip_mag(float v, float mx) {
    // matches jnp.where(|v| >= mx, v * |mx/v|, v) incl. inf -> NaN edge case
    if (fabsf(v) >= mx) v = v * fabsf(mx / v);
    return v;
}

// ---- prep: tightly pack W rows (row-major, exact DIN), append Wf ----
__global__ void netnew_prep(PrepParams pp) {
#define STAGE_LAYER(L)                                                        \
    {                                                                         \
        constexpr int D = LC<L>::DIN;                                         \
        const float* g = pp.W[L];                                             \
        for (int i = threadIdx.x; i < 13 * D; i += blockDim.x)                \
            g_wpad[WOff<L>::V + i] = g[i];                                    \
    }
    STAGE_LAYER(0) STAGE_LAYER(1) STAGE_LAYER(2) STAGE_LAYER(3)
    STAGE_LAYER(4) STAGE_LAYER(5) STAGE_LAYER(6) STAGE_LAYER(7)
#undef STAGE_LAYER
    for (int i = threadIdx.x; i < 80; i += blockDim.x)
        g_wpad[WF_OFF + i] = pp.W[8][i];
}

template <int L>
__device__ __forceinline__ void do_layer(float* __restrict__ h) {
    constexpr int DIN  = LC<L>::DIN;
    constexpr int BASE = LC<L>::BASE;
    constexpr int K4   = DIN & ~3;       // vectorizable prefix
    // NOTE: row j starts at WOff + j*DIN. With DIN odd or %4!=0, alignment of
    // each row varies; rows are float-aligned always. Use element loads via
    // float4 only when 16B-aligned at compile time -> instead address rows
    // individually: row offset j*DIN known at compile time, so alignment of
    // (WOff + j*DIN) % 4 is compile-time; pick vector widths accordingly.

    float z[13];
#pragma unroll
    for (int j = 0; j < 13; ++j) {
        constexpr int ROWSTART_DUMMY = 0; (void)ROWSTART_DUMMY;
        const int roff = WOff<L>::V + j * DIN;   // compile-time after unroll
        float acc = 0.0f;
        int k = 0;
        // alignment of roff in floats (0..3), compile-time constant per j
        const int mis = roff & 3;
        // peel to 16B alignment
        if (mis != 0) {
            const int peel = 4 - mis;
#pragma unroll
            for (int t = 0; t < 3; ++t) {
                if (t < peel && k < DIN) {
                    acc = fmaf(cw[roff + k], h[BASE + k], acc);
                    ++k;
                }
            }
        }
        // aligned float4 body
#pragma unroll
        for (; k + 3 < DIN; k += 4) {
            const float4 w = *reinterpret_cast<const float4*>(cw + roff + k);
            acc = fmaf(w.x, h[BASE + k + 0], acc);
            acc = fmaf(w.y, h[BASE + k + 1], acc);
            acc = fmaf(w.z, h[BASE + k + 2], acc);
            acc = fmaf(w.w, h[BASE + k + 3], acc);
        }
        // tail
#pragma unroll
        for (; k < DIN; ++k)
            acc = fmaf(cw[roff + k], h[BASE + k], acc);
        z[j] = acc;
        (void)K4;
    }

    float* o = h + (BASE - 9);
    o[0] = z[0] + z[1];
    o[1] = z[2] - z[3];
    o[2] = clip_mag(z[4] * z[5], 99999999.0f);
    {
        float b   = z[7];
        float den = (b == 0.0f) ? (b + 0.0001f) : b;
        o[3] = clip_mag(z[6] / den, 9999.0f);
    }
    o[4] = sinf(z[8]);
    o[5] = cosf(z[9]);
    {
        float a = z[10];
        if (a >= 17.0f) a = a * (17.0f / a);
        o[6] = expf(a);
    }
    o[7] = logf(fabsf(z[11]));
    o[8] = clip_mag(z[12] * z[12], 99999999.0f);
}

__global__ __launch_bounds__(96, 7)
void netnew_kernel7(NetParams p) {
    const int row = blockIdx.x * blockDim.x + threadIdx.x;
    if (row >= p.B) return;

    // h layout: [outs8 | outs7 | ... | outs1 | x]; x at [72..79].
    float h[80];
    {
        const float4* xr = reinterpret_cast<const float4*>(p.x + (size_t)row * 8);
        float4 a = xr[0], b = xr[1];
        h[72] = a.x; h[73] = a.y; h[74] = a.z; h[75] = a.w;
        h[76] = b.x; h[77] = b.y; h[78] = b.z; h[79] = b.w;
    }

    do_layer<0>(h);
    do_layer<1>(h);
    do_layer<2>(h);
    do_layer<3>(h);
    do_layer<4>(h);
    do_layer<5>(h);
    do_layer<6>(h);
    do_layer<7>(h);

    // final: out = dot(Wf, h[0..79]), sequential ascending k (WF_OFF%4==0)
    float acc = 0.0f;
#pragma unroll
    for (int k = 0; k < 80; k += 4) {
        const float4 w = *reinterpret_cast<const float4*>(cw + WF_OFF + k);
        acc = fmaf(w.x, h[k + 0], acc);
        acc = fmaf(w.y, h[k + 1], acc);
        acc = fmaf(w.z, h[k + 2], acc);
        acc = fmaf(w.w, h[k + 3], acc);
    }
    p.out[row] = acc;
}

extern "C" void kernel_launch(void* const* d_in, const int* in_sizes, int n_in,
                              void* d_out, int out_size) {
    PrepParams pp;
    for (int i = 0; i < 9; ++i) pp.W[i] = (const float*)d_in[1 + i];

    NetParams p;
    p.x   = (const float*)d_in[0];
    p.out = (float*)d_out;
    p.B   = in_sizes[0] / 8;

    // 1) pack weights into device scratch
    netnew_prep<<<1, 256>>>(pp);

    // 2) scratch -> constant bank (D2D, graph-capturable)
    void* src = nullptr;
    cudaGetSymbolAddress(&src, g_wpad);
    cudaMemcpyToSymbolAsync(cw, src, CW_TOTAL * sizeof(float), 0,
                            cudaMemcpyDeviceToDevice, 0);

    // 3) main kernel
    const int threads = 96;
    const int blocks  = (p.B + threads - 1) / threads;
    netnew_kernel7<<<blocks, threads>>>(p);
}